// round 14
// baseline (speedup 1.0000x reference)
#include <cuda_runtime.h>
#include <cuda_fp16.h>
#include <math.h>
#include <stdint.h>

#define D_MODEL 2048
#define N_HEADS 16
#define HEAD_DIM 128
#define SEQ 2048
#define BATCH 2
#define MROWS (BATCH*SEQ)   // 4096
#define NQKV (3*D_MODEL)    // 6144

// Scratch (static device globals; no allocation allowed)
__device__ __half g_qkvh[(size_t)MROWS * NQKV];
__device__ __half g_qh[(size_t)MROWS * D_MODEL];
__device__ __half g_kh[(size_t)MROWS * D_MODEL];
__device__ __half g_vh[(size_t)MROWS * D_MODEL];
__device__ __half g_xh[(size_t)MROWS * D_MODEL];
__device__ __half g_oh[(size_t)MROWS * D_MODEL];
__device__ __half g_wh[4][(size_t)D_MODEL * D_MODEL];

// ---------------------------------------------------------------------------
// helpers
// ---------------------------------------------------------------------------
#define NX4 ((MROWS * D_MODEL) / 4)
#define NW4 ((D_MODEL * D_MODEL) / 4)

__global__ void f2h_all(const float4* __restrict__ X,
                        const float4* __restrict__ Wq, const float4* __restrict__ Wk,
                        const float4* __restrict__ Wv, const float4* __restrict__ Wo,
                        uint2* __restrict__ xh, uint2* __restrict__ wh)
{
    int i = blockIdx.x * blockDim.x + threadIdx.x;
    const float4* src;
    uint2* dst;
    if (i < NX4) {
        src = X + i; dst = xh + i;
    } else {
        int j = i - NX4;
        int r = j / NW4;
        int o = j - r * NW4;
        const float4* ws[4] = {Wq, Wk, Wv, Wo};
        src = ws[r] + o;
        dst = wh + (size_t)r * NW4 + o;
    }
    float4 v = *src;
    __half2 h01 = __floats2half2_rn(v.x, v.y);
    __half2 h23 = __floats2half2_rn(v.z, v.w);
    *dst = make_uint2(*(uint32_t*)&h01, *(uint32_t*)&h23);
}

__device__ __forceinline__ void cpa16s(uint32_t saddr, const void* g) {
    asm volatile("cp.async.cg.shared.global [%0], [%1], 16;" :: "r"(saddr), "l"(g));
}

__device__ __forceinline__ uint32_t s2u(const void* p) {
    uint32_t a;
    asm("{ .reg .u64 t; cvta.to.shared.u64 t, %1; cvt.u32.u64 %0, t; }" : "=r"(a) : "l"(p));
    return a;
}

__device__ __forceinline__ void mma_f16(float* c,
                                        uint32_t a0, uint32_t a1, uint32_t a2, uint32_t a3,
                                        uint32_t b0, uint32_t b1)
{
    asm volatile(
        "mma.sync.aligned.m16n8k16.row.col.f32.f16.f16.f32 "
        "{%0,%1,%2,%3},{%4,%5,%6,%7},{%8,%9},{%0,%1,%2,%3};"
        : "+f"(c[0]), "+f"(c[1]), "+f"(c[2]), "+f"(c[3])
        : "r"(a0), "r"(a1), "r"(a2), "r"(a3), "r"(b0), "r"(b1));
}

#define LDSM_X4(R0,R1,R2,R3,ADDR) \
    asm volatile("ldmatrix.sync.aligned.m8n8.x4.shared.b16 {%0,%1,%2,%3}, [%4];" \
        : "=r"(R0), "=r"(R1), "=r"(R2), "=r"(R3) : "r"(ADDR))

#define LDSM_X4T(R0,R1,R2,R3,ADDR) \
    asm volatile("ldmatrix.sync.aligned.m8n8.x4.trans.shared.b16 {%0,%1,%2,%3}, [%4];" \
        : "=r"(R0), "=r"(R1), "=r"(R2), "=r"(R3) : "r"(ADDR))

__device__ __forceinline__ uint32_t packh2(float a, float b) {
    __half2 h = __floats2half2_rn(a, b);
    return *(uint32_t*)&h;
}

#define HROWB 144

// ---------------------------------------------------------------------------
// fp16 GEMM NT 128x128, 8 warps (32x64 each), 256 thr, 3-stage, 2 CTA/SM.
// 16 warps/SM; regs capped at 128 by launch_bounds.
// ---------------------------------------------------------------------------
#define HBM 128
#define HBK 64
#define STAGE_BYTES (2 * HBM * HROWB)
#define GEMMH_SMEM (3 * STAGE_BYTES)      // 110592 bytes

template<bool HALF_OUT>
__global__ __launch_bounds__(256, 2) void gemm_f16(const __half* __restrict__ A,
                                                   const __half* __restrict__ B,
                                                   void* __restrict__ Cv,
                                                   int M, int N, int K)
{
    extern __shared__ char smraw[];
    const uint32_t sb = s2u(smraw);

    const int tid  = threadIdx.x;
    const int warp = tid >> 5;
    const int lane = tid & 31;
    const int wm = (warp >> 1) * 32;   // 0,32,64,96
    const int wn = (warp & 1) * 64;    // 0,64
    const int lr = lane >> 2;
    const int lc = lane & 3;

    const int m0 = blockIdx.y * HBM;
    const int n0 = blockIdx.x * 128;

    const int ldr  = tid >> 3;          // 0..31
    const int ldch = (tid & 7) * 16;

    const char* Ab = (const char*)(A + (size_t)m0 * K);
    const char* Bb = (const char*)(B + (size_t)n0 * K);

    uint32_t aOff[2], bOff[4];
    #pragma unroll
    for (int mt = 0; mt < 2; mt++)
        aOff[mt] = (wm + mt * 16 + (lane & 15)) * HROWB + ((lane & 16) ? 16 : 0);
    #pragma unroll
    for (int ntp = 0; ntp < 4; ntp++)
        bOff[ntp] = HBM * HROWB
                  + (wn + (2 * ntp + ((lane & 16) ? 1 : 0)) * 8 + (lane & 7)) * HROWB
                  + ((lane & 8) ? 16 : 0);

    float c[2][8][4];
    #pragma unroll
    for (int i = 0; i < 2; i++)
        #pragma unroll
        for (int j = 0; j < 8; j++)
            #pragma unroll
            for (int e = 0; e < 4; e++) c[i][j][e] = 0.f;

    const int nk = K / HBK;

    // prologue: tiles 0,1 -> stages 0,1
    #pragma unroll
    for (int st = 0; st < 2; st++) {
        const size_t kb = (size_t)st * HBK * 2;
        const uint32_t dA = sb + st * STAGE_BYTES;
        const uint32_t dB = dA + HBM * HROWB;
        #pragma unroll
        for (int i = 0; i < 4; i++) {
            int r = ldr + 32 * i;
            cpa16s(dA + r * HROWB + ldch, Ab + (size_t)r * K * 2 + kb + ldch);
            cpa16s(dB + r * HROWB + ldch, Bb + (size_t)r * K * 2 + kb + ldch);
        }
        asm volatile("cp.async.commit_group;");
    }

    int stcur = 0, stnext = 2;
    for (int kt = 0; kt < nk; kt++) {
        if (kt + 2 < nk)
            asm volatile("cp.async.wait_group 1;");
        else
            asm volatile("cp.async.wait_group 0;");
        __syncthreads();

        if (kt + 2 < nk) {
            const size_t kb = (size_t)(kt + 2) * HBK * 2;
            const uint32_t dA = sb + stnext * STAGE_BYTES;
            const uint32_t dB = dA + HBM * HROWB;
            #pragma unroll
            for (int i = 0; i < 4; i++) {
                int r = ldr + 32 * i;
                cpa16s(dA + r * HROWB + ldch, Ab + (size_t)r * K * 2 + kb + ldch);
                cpa16s(dB + r * HROWB + ldch, Bb + (size_t)r * K * 2 + kb + ldch);
            }
            asm volatile("cp.async.commit_group;");
        }

        const uint32_t buf = sb + stcur * STAGE_BYTES;

        #pragma unroll
        for (int ks = 0; ks < 4; ks++) {
            uint32_t a[2][4], b[4][4];
            #pragma unroll
            for (int mt = 0; mt < 2; mt++)
                LDSM_X4(a[mt][0], a[mt][1], a[mt][2], a[mt][3],
                        buf + aOff[mt] + ks * 32);
            #pragma unroll
            for (int ntp = 0; ntp < 4; ntp++)
                LDSM_X4(b[ntp][0], b[ntp][1], b[ntp][2], b[ntp][3],
                        buf + bOff[ntp] + ks * 32);
            #pragma unroll
            for (int mt = 0; mt < 2; mt++)
                #pragma unroll
                for (int nt = 0; nt < 8; nt++)
                    mma_f16(c[mt][nt], a[mt][0], a[mt][1], a[mt][2], a[mt][3],
                            b[nt >> 1][(nt & 1) * 2], b[nt >> 1][(nt & 1) * 2 + 1]);
        }

        stcur  = (stcur == 2)  ? 0 : stcur + 1;
        stnext = (stnext == 2) ? 0 : stnext + 1;
    }

    #pragma unroll
    for (int mt = 0; mt < 2; mt++) {
        #pragma unroll
        for (int nt = 0; nt < 8; nt++) {
            int row = m0 + wm + mt * 16 + lr;
            int col = n0 + wn + nt * 8 + 2 * lc;
            if (HALF_OUT) {
                __half* C = (__half*)Cv;
                *(uint32_t*)(C + (size_t)row * N + col)       = packh2(c[mt][nt][0], c[mt][nt][1]);
                *(uint32_t*)(C + (size_t)(row + 8) * N + col) = packh2(c[mt][nt][2], c[mt][nt][3]);
            } else {
                float* C = (float*)Cv;
                *(float2*)(C + (size_t)row * N + col)       = make_float2(c[mt][nt][0], c[mt][nt][1]);
                *(float2*)(C + (size_t)(row + 8) * N + col) = make_float2(c[mt][nt][2], c[mt][nt][3]);
            }
        }
    }
}

// ---------------------------------------------------------------------------
// Fused RoPE, vectorized half2.
// ---------------------------------------------------------------------------
__global__ void rope_f16(const __half* __restrict__ QKV,
                         __half* __restrict__ Qh, __half* __restrict__ Kh,
                         __half* __restrict__ Vh)
{
    int idx = blockIdx.x * blockDim.x + threadIdx.x;
    if (idx >= MROWS * N_HEADS * 32) return;
    int j2  = idx & 31;
    int j   = 2 * j2;
    int h   = (idx >> 5) & (N_HEADS - 1);
    int row = idx >> 9;
    int s   = row & (SEQ - 1);

    const float c0 = 13.287712379549449f / 64.0f;
    float sn0, cs0, sn1, cs1;
    sincosf((float)s * exp2f(-(float)j * c0),       &sn0, &cs0);
    sincosf((float)s * exp2f(-(float)(j + 1) * c0), &sn1, &cs1);
    const float scale = 0.088388347648318447f;

    size_t bin  = (size_t)row * NQKV + h * HEAD_DIM + j;
    size_t bout = (size_t)row * D_MODEL + h * HEAD_DIM + j;

    __half2 qlo = *(const __half2*)(QKV + bin);
    __half2 qhi = *(const __half2*)(QKV + bin + 64);
    float2 q1 = __half22float2(qlo), q2 = __half22float2(qhi);
    *(uint32_t*)(Qh + bout)      = packh2((q1.x * cs0 - q2.x * sn0) * scale,
                                          (q1.y * cs1 - q2.y * sn1) * scale);
    *(uint32_t*)(Qh + bout + 64) = packh2((q2.x * cs0 + q1.x * sn0) * scale,
                                          (q2.y * cs1 + q1.y * sn1) * scale);

    __half2 klo = *(const __half2*)(QKV + bin + D_MODEL);
    __half2 khi = *(const __half2*)(QKV + bin + D_MODEL + 64);
    float2 k1 = __half22float2(klo), k2 = __half22float2(khi);
    *(uint32_t*)(Kh + bout)      = packh2(k1.x * cs0 - k2.x * sn0,
                                          k1.y * cs1 - k2.y * sn1);
    *(uint32_t*)(Kh + bout + 64) = packh2(k2.x * cs0 + k1.x * sn0,
                                          k2.y * cs1 + k1.y * sn1);

    *(uint32_t*)(Vh + bout)      = *(const uint32_t*)(QKV + bin + 2 * D_MODEL);
    *(uint32_t*)(Vh + bout + 64) = *(const uint32_t*)(QKV + bin + 2 * D_MODEL + 64);
}

// ---------------------------------------------------------------------------
// Flash attention, fp16 mma. 64 q-rows/block, 4 warps, 2 CTAs/SM. (R12 proven)
// ---------------------------------------------------------------------------
#define QSH 136
#define AQ_ROWS 64
#define OFF_KV (AQ_ROWS*QSH)               // halves
#define KVBUF  (64*QSH)
#define ATTN_SMEM_BYTES ((AQ_ROWS*QSH + 4*KVBUF) * 2)   // 87040

__global__ __launch_bounds__(128, 2) void attn_f16(const __half* __restrict__ Q,
                                                   const __half* __restrict__ K,
                                                   const __half* __restrict__ V,
                                                   __half* __restrict__ O)
{
    extern __shared__ char smraw[];
    const uint32_t sb = s2u(smraw);

    const int tid  = threadIdx.x;
    const int warp = tid >> 5;
    const int lane = tid & 31;
    const int lr = lane >> 2;
    const int lc = lane & 3;
    const int wm = warp * 16;

    const int qx = gridDim.x - 1 - blockIdx.x;   // heavy CTAs first
    const int q0 = qx * AQ_ROWS;
    const int b  = blockIdx.y >> 4;
    const int h  = blockIdx.y & (N_HEADS - 1);

    const __half* Qb = Q + ((size_t)(b * SEQ + q0)) * D_MODEL + h * HEAD_DIM;
    const __half* Kb = K + ((size_t)(b * SEQ)) * D_MODEL + h * HEAD_DIM;
    const __half* Vb = V + ((size_t)(b * SEQ)) * D_MODEL + h * HEAD_DIM;

    const uint32_t aQoff = ((wm + (lane & 15)) * QSH + ((lane & 16) ? 8 : 0)) * 2;
    uint32_t bKoff[4];
    #pragma unroll
    for (int ntp = 0; ntp < 4; ntp++)
        bKoff[ntp] = (((2 * ntp + ((lane & 16) ? 1 : 0)) * 8 + (lane & 7)) * QSH
                      + ((lane & 8) ? 8 : 0)) * 2;
    uint32_t bVoff[8];
    #pragma unroll
    for (int ntp = 0; ntp < 8; ntp++)
        bVoff[ntp] = ((lane & 15) * QSH + (2 * ntp + ((lane & 16) ? 1 : 0)) * 8) * 2;

    {
        #pragma unroll
        for (int i = 0; i < 8; i++) {
            int p = tid + 128 * i;
            int r = p >> 4, ch = p & 15;
            cpa16s(sb + (r * QSH) * 2 + ch * 16, Qb + (size_t)r * D_MODEL + ch * 8);
            cpa16s(sb + (OFF_KV + r * QSH) * 2 + ch * 16,         Kb + (size_t)r * D_MODEL + ch * 8);
            cpa16s(sb + (OFF_KV + KVBUF + r * QSH) * 2 + ch * 16, Vb + (size_t)r * D_MODEL + ch * 8);
        }
        asm volatile("cp.async.commit_group;");
    }

    uint32_t qf[8][4];
    float o_acc[16][4];
    #pragma unroll
    for (int i = 0; i < 16; i++)
        #pragma unroll
        for (int e = 0; e < 4; e++) o_acc[i][e] = 0.f;
    float m0 = -1e30f, m1 = -1e30f, l0 = 0.f, l1 = 0.f;

    const int r0g = q0 + wm + lr;
    const int r1g = r0g + 8;

    const int ntiles = qx + 1;
    for (int kt = 0; kt < ntiles; kt++) {
        asm volatile("cp.async.wait_group 0;");
        __syncthreads();

        if (kt == 0) {
            #pragma unroll
            for (int ks = 0; ks < 8; ks++)
                LDSM_X4(qf[ks][0], qf[ks][1], qf[ks][2], qf[ks][3],
                        sb + aQoff + ks * 32);
        }

        if (kt + 1 < ntiles) {
            const int nb = (kt + 1) & 1;
            const uint32_t dK = sb + (OFF_KV + nb * 2 * KVBUF) * 2;
            const uint32_t dV = dK + KVBUF * 2;
            const size_t krow = (size_t)(kt + 1) * 64;
            #pragma unroll
            for (int i = 0; i < 8; i++) {
                int p = tid + 128 * i;
                int r = p >> 4, ch = p & 15;
                cpa16s(dK + (r * QSH) * 2 + ch * 16, Kb + (krow + r) * D_MODEL + ch * 8);
                cpa16s(dV + (r * QSH) * 2 + ch * 16, Vb + (krow + r) * D_MODEL + ch * 8);
            }
            asm volatile("cp.async.commit_group;");
        }

        const uint32_t bufK = sb + (OFF_KV + (kt & 1) * 2 * KVBUF) * 2;
        const uint32_t bufV = bufK + KVBUF * 2;
        const int k0 = kt * 64;

        float s[8][4];
        #pragma unroll
        for (int nt = 0; nt < 8; nt++)
            #pragma unroll
            for (int e = 0; e < 4; e++) s[nt][e] = 0.f;

        #pragma unroll
        for (int ks = 0; ks < 8; ks++) {
            #pragma unroll
            for (int ntp = 0; ntp < 4; ntp++) {
                uint32_t b0, b1, b2, b3;
                LDSM_X4(b0, b1, b2, b3, bufK + bKoff[ntp] + ks * 32);
                mma_f16(s[2 * ntp],     qf[ks][0], qf[ks][1], qf[ks][2], qf[ks][3], b0, b1);
                mma_f16(s[2 * ntp + 1], qf[ks][0], qf[ks][1], qf[ks][2], qf[ks][3], b2, b3);
            }
        }

        float rm0 = -1e30f, rm1 = -1e30f;
        #pragma unroll
        for (int nt = 0; nt < 8; nt++) {
            int c0 = k0 + nt * 8 + 2 * lc;
            if (c0     > r0g) s[nt][0] = -1e30f;
            if (c0 + 1 > r0g) s[nt][1] = -1e30f;
            if (c0     > r1g) s[nt][2] = -1e30f;
            if (c0 + 1 > r1g) s[nt][3] = -1e30f;
            rm0 = fmaxf(rm0, fmaxf(s[nt][0], s[nt][1]));
            rm1 = fmaxf(rm1, fmaxf(s[nt][2], s[nt][3]));
        }
        rm0 = fmaxf(rm0, __shfl_xor_sync(0xffffffffu, rm0, 1));
        rm0 = fmaxf(rm0, __shfl_xor_sync(0xffffffffu, rm0, 2));
        rm1 = fmaxf(rm1, __shfl_xor_sync(0xffffffffu, rm1, 1));
        rm1 = fmaxf(rm1, __shfl_xor_sync(0xffffffffu, rm1, 2));

        float mn0 = fmaxf(m0, rm0), mn1 = fmaxf(m1, rm1);
        float al0 = __expf(m0 - mn0), al1 = __expf(m1 - mn1);
        m0 = mn0; m1 = mn1;

        float ps0 = 0.f, ps1 = 0.f;
        uint32_t pa[8], pb[8];
        #pragma unroll
        for (int nt = 0; nt < 8; nt++) {
            float p00 = __expf(s[nt][0] - mn0);
            float p01 = __expf(s[nt][1] - mn0);
            float p10 = __expf(s[nt][2] - mn1);
            float p11 = __expf(s[nt][3] - mn1);
            ps0 += p00 + p01;
            ps1 += p10 + p11;
            pa[nt] = packh2(p00, p01);
            pb[nt] = packh2(p10, p11);
        }
        ps0 += __shfl_xor_sync(0xffffffffu, ps0, 1);
        ps0 += __shfl_xor_sync(0xffffffffu, ps0, 2);
        ps1 += __shfl_xor_sync(0xffffffffu, ps1, 1);
        ps1 += __shfl_xor_sync(0xffffffffu, ps1, 2);
        l0 = l0 * al0 + ps0;
        l1 = l1 * al1 + ps1;

        #pragma unroll
        for (int nt2 = 0; nt2 < 16; nt2++) {
            o_acc[nt2][0] *= al0; o_acc[nt2][1] *= al0;
            o_acc[nt2][2] *= al1; o_acc[nt2][3] *= al1;
        }

        #pragma unroll
        for (int j = 0; j < 4; j++) {
            uint32_t a0 = pa[2 * j],     a1 = pb[2 * j];
            uint32_t a2 = pa[2 * j + 1], a3 = pb[2 * j + 1];
            #pragma unroll
            for (int ntp = 0; ntp < 8; ntp++) {
                uint32_t b0, b1, b2, b3;
                LDSM_X4T(b0, b1, b2, b3, bufV + bVoff[ntp] + j * 16 * QSH * 2);
                mma_f16(o_acc[2 * ntp],     a0, a1, a2, a3, b0, b1);
                mma_f16(o_acc[2 * ntp + 1], a0, a1, a2, a3, b2, b3);
            }
        }
    }

    float inv0 = 1.0f / l0, inv1 = 1.0f / l1;
    __half* Ob = O + ((size_t)(b * SEQ + q0 + wm + lr)) * D_MODEL + h * HEAD_DIM;
    #pragma unroll
    for (int nt2 = 0; nt2 < 16; nt2++) {
        int col = nt2 * 8 + 2 * lc;
        *(uint32_t*)(Ob + col)               = packh2(o_acc[nt2][0] * inv0, o_acc[nt2][1] * inv0);
        *(uint32_t*)(Ob + 8 * D_MODEL + col) = packh2(o_acc[nt2][2] * inv1, o_acc[nt2][3] * inv1);
    }
}

// ---------------------------------------------------------------------------
extern "C" void kernel_launch(void* const* d_in, const int* in_sizes, int n_in,
                              void* d_out, int out_size)
{
    const float* X  = (const float*)d_in[0];
    const float* Wq = (const float*)d_in[1];
    const float* Wk = (const float*)d_in[2];
    const float* Wv = (const float*)d_in[3];
    const float* Wo = (const float*)d_in[4];
    float* out = (float*)d_out;

    __half *qkvh, *qh, *kh, *vh, *xh, *oh, *wh;
    cudaGetSymbolAddress((void**)&qkvh, g_qkvh);
    cudaGetSymbolAddress((void**)&qh, g_qh);
    cudaGetSymbolAddress((void**)&kh, g_kh);
    cudaGetSymbolAddress((void**)&vh, g_vh);
    cudaGetSymbolAddress((void**)&xh, g_xh);
    cudaGetSymbolAddress((void**)&oh, g_oh);
    cudaGetSymbolAddress((void**)&wh, g_wh);
    __half* woh = wh + 3 * (size_t)D_MODEL * D_MODEL;

    cudaFuncSetAttribute(attn_f16, cudaFuncAttributeMaxDynamicSharedMemorySize,
                         ATTN_SMEM_BYTES);
    cudaFuncSetAttribute(gemm_f16<true>, cudaFuncAttributeMaxDynamicSharedMemorySize,
                         GEMMH_SMEM);
    cudaFuncSetAttribute(gemm_f16<false>, cudaFuncAttributeMaxDynamicSharedMemorySize,
                         GEMMH_SMEM);

    // 1) fp16 conversion of all operands, single launch
    {
        int ntot = NX4 + 4 * NW4;
        f2h_all<<<(ntot + 255) / 256, 256>>>(
            (const float4*)X, (const float4*)Wq, (const float4*)Wk,
            (const float4*)Wv, (const float4*)Wo, (uint2*)xh, (uint2*)wh);
    }

    // 2) fused QKV projection (256-thread CTAs, 16 warps/SM)
    gemm_f16<true><<<dim3(NQKV / 128, MROWS / HBM), 256, GEMMH_SMEM>>>(
        xh, wh, qkvh, MROWS, NQKV, D_MODEL);

    // 3) fused RoPE (+ Q pre-scale), half2-vectorized
    rope_f16<<<(MROWS * N_HEADS * 32) / 256, 256>>>(qkvh, qh, kh, vh);

    // 4) attention (64 q-rows/CTA, 2 CTAs/SM)
    attn_f16<<<dim3(SEQ / AQ_ROWS, BATCH * N_HEADS), 128, ATTN_SMEM_BYTES>>>(qh, kh, vh, oh);

    // 5) output projection (fp32 out)
    gemm_f16<false><<<dim3(D_MODEL / 128, MROWS / HBM), 256, GEMMH_SMEM>>>(
        oh, woh, out, MROWS, D_MODEL, D_MODEL);
}

// round 15
// speedup vs baseline: 1.0155x; 1.0155x over previous
#include <cuda_runtime.h>
#include <cuda_fp16.h>
#include <math.h>
#include <stdint.h>

#define D_MODEL 2048
#define N_HEADS 16
#define HEAD_DIM 128
#define SEQ 2048
#define BATCH 2
#define MROWS (BATCH*SEQ)   // 4096
#define NQKV (3*D_MODEL)    // 6144

// Scratch (static device globals; no allocation allowed)
__device__ __half g_qkvh[(size_t)MROWS * NQKV];
__device__ __half g_qh[(size_t)MROWS * D_MODEL];
__device__ __half g_kh[(size_t)MROWS * D_MODEL];
__device__ __half g_vh[(size_t)MROWS * D_MODEL];
__device__ __half g_xh[(size_t)MROWS * D_MODEL];
__device__ __half g_oh[(size_t)MROWS * D_MODEL];
__device__ __half g_wh[4][(size_t)D_MODEL * D_MODEL];

// ---------------------------------------------------------------------------
// helpers
// ---------------------------------------------------------------------------
#define NX4 ((MROWS * D_MODEL) / 4)
#define NW4 ((D_MODEL * D_MODEL) / 4)

__global__ void f2h_all(const float4* __restrict__ X,
                        const float4* __restrict__ Wq, const float4* __restrict__ Wk,
                        const float4* __restrict__ Wv, const float4* __restrict__ Wo,
                        uint2* __restrict__ xh, uint2* __restrict__ wh)
{
    int i = blockIdx.x * blockDim.x + threadIdx.x;
    const float4* src;
    uint2* dst;
    if (i < NX4) {
        src = X + i; dst = xh + i;
    } else {
        int j = i - NX4;
        int r = j / NW4;
        int o = j - r * NW4;
        const float4* ws[4] = {Wq, Wk, Wv, Wo};
        src = ws[r] + o;
        dst = wh + (size_t)r * NW4 + o;
    }
    float4 v = *src;
    __half2 h01 = __floats2half2_rn(v.x, v.y);
    __half2 h23 = __floats2half2_rn(v.z, v.w);
    *dst = make_uint2(*(uint32_t*)&h01, *(uint32_t*)&h23);
}

__device__ __forceinline__ void cpa16s(uint32_t saddr, const void* g) {
    asm volatile("cp.async.cg.shared.global [%0], [%1], 16;" :: "r"(saddr), "l"(g));
}

__device__ __forceinline__ uint32_t s2u(const void* p) {
    uint32_t a;
    asm("{ .reg .u64 t; cvta.to.shared.u64 t, %1; cvt.u32.u64 %0, t; }" : "=r"(a) : "l"(p));
    return a;
}

__device__ __forceinline__ void mma_f16(float* c,
                                        uint32_t a0, uint32_t a1, uint32_t a2, uint32_t a3,
                                        uint32_t b0, uint32_t b1)
{
    asm volatile(
        "mma.sync.aligned.m16n8k16.row.col.f32.f16.f16.f32 "
        "{%0,%1,%2,%3},{%4,%5,%6,%7},{%8,%9},{%0,%1,%2,%3};"
        : "+f"(c[0]), "+f"(c[1]), "+f"(c[2]), "+f"(c[3])
        : "r"(a0), "r"(a1), "r"(a2), "r"(a3), "r"(b0), "r"(b1));
}

#define LDSM_X4(R0,R1,R2,R3,ADDR) \
    asm volatile("ldmatrix.sync.aligned.m8n8.x4.shared.b16 {%0,%1,%2,%3}, [%4];" \
        : "=r"(R0), "=r"(R1), "=r"(R2), "=r"(R3) : "r"(ADDR))

#define LDSM_X4T(R0,R1,R2,R3,ADDR) \
    asm volatile("ldmatrix.sync.aligned.m8n8.x4.trans.shared.b16 {%0,%1,%2,%3}, [%4];" \
        : "=r"(R0), "=r"(R1), "=r"(R2), "=r"(R3) : "r"(ADDR))

__device__ __forceinline__ uint32_t packh2(float a, float b) {
    __half2 h = __floats2half2_rn(a, b);
    return *(uint32_t*)&h;
}

#define HROWB 144

// ---------------------------------------------------------------------------
// fp16 GEMM NT 128x128, 4 warps (64x64), 3-stage cp.async, 2 CTA/SM. (R11)
// ---------------------------------------------------------------------------
#define HBM 128
#define HBK 64
#define STAGE_BYTES (2 * HBM * HROWB)
#define GEMMH_SMEM (3 * STAGE_BYTES)      // 110592 bytes

template<bool HALF_OUT>
__global__ __launch_bounds__(128, 2) void gemm_f16(const __half* __restrict__ A,
                                                   const __half* __restrict__ B,
                                                   void* __restrict__ Cv,
                                                   int M, int N, int K)
{
    extern __shared__ char smraw[];
    const uint32_t sb = s2u(smraw);

    const int tid  = threadIdx.x;
    const int warp = tid >> 5;
    const int lane = tid & 31;
    const int wm = (warp >> 1) * 64;
    const int wn = (warp & 1) * 64;
    const int lr = lane >> 2;
    const int lc = lane & 3;

    const int m0 = blockIdx.y * HBM;
    const int n0 = blockIdx.x * 128;

    const int ldr  = tid >> 3;
    const int ldch = (tid & 7) * 16;

    const char* Ab = (const char*)(A + (size_t)m0 * K);
    const char* Bb = (const char*)(B + (size_t)n0 * K);

    uint32_t aOff[4], bOff[4];
    #pragma unroll
    for (int mt = 0; mt < 4; mt++)
        aOff[mt] = (wm + mt * 16 + (lane & 15)) * HROWB + ((lane & 16) ? 16 : 0);
    #pragma unroll
    for (int ntp = 0; ntp < 4; ntp++)
        bOff[ntp] = HBM * HROWB
                  + (wn + (2 * ntp + ((lane & 16) ? 1 : 0)) * 8 + (lane & 7)) * HROWB
                  + ((lane & 8) ? 16 : 0);

    float c[4][8][4];
    #pragma unroll
    for (int i = 0; i < 4; i++)
        #pragma unroll
        for (int j = 0; j < 8; j++)
            #pragma unroll
            for (int e = 0; e < 4; e++) c[i][j][e] = 0.f;

    const int nk = K / HBK;

    #pragma unroll
    for (int st = 0; st < 2; st++) {
        const size_t kb = (size_t)st * HBK * 2;
        const uint32_t dA = sb + st * STAGE_BYTES;
        const uint32_t dB = dA + HBM * HROWB;
        #pragma unroll
        for (int i = 0; i < 8; i++) {
            int r = ldr + 16 * i;
            cpa16s(dA + r * HROWB + ldch, Ab + (size_t)r * K * 2 + kb + ldch);
            cpa16s(dB + r * HROWB + ldch, Bb + (size_t)r * K * 2 + kb + ldch);
        }
        asm volatile("cp.async.commit_group;");
    }

    int stcur = 0, stnext = 2;
    for (int kt = 0; kt < nk; kt++) {
        if (kt + 2 < nk)
            asm volatile("cp.async.wait_group 1;");
        else
            asm volatile("cp.async.wait_group 0;");
        __syncthreads();

        if (kt + 2 < nk) {
            const size_t kb = (size_t)(kt + 2) * HBK * 2;
            const uint32_t dA = sb + stnext * STAGE_BYTES;
            const uint32_t dB = dA + HBM * HROWB;
            #pragma unroll
            for (int i = 0; i < 8; i++) {
                int r = ldr + 16 * i;
                cpa16s(dA + r * HROWB + ldch, Ab + (size_t)r * K * 2 + kb + ldch);
                cpa16s(dB + r * HROWB + ldch, Bb + (size_t)r * K * 2 + kb + ldch);
            }
            asm volatile("cp.async.commit_group;");
        }

        const uint32_t buf = sb + stcur * STAGE_BYTES;

        #pragma unroll
        for (int ks = 0; ks < 4; ks++) {
            uint32_t a[4][4], b[4][4];
            #pragma unroll
            for (int mt = 0; mt < 4; mt++)
                LDSM_X4(a[mt][0], a[mt][1], a[mt][2], a[mt][3],
                        buf + aOff[mt] + ks * 32);
            #pragma unroll
            for (int ntp = 0; ntp < 4; ntp++)
                LDSM_X4(b[ntp][0], b[ntp][1], b[ntp][2], b[ntp][3],
                        buf + bOff[ntp] + ks * 32);
            #pragma unroll
            for (int mt = 0; mt < 4; mt++)
                #pragma unroll
                for (int nt = 0; nt < 8; nt++)
                    mma_f16(c[mt][nt], a[mt][0], a[mt][1], a[mt][2], a[mt][3],
                            b[nt >> 1][(nt & 1) * 2], b[nt >> 1][(nt & 1) * 2 + 1]);
        }

        stcur  = (stcur == 2)  ? 0 : stcur + 1;
        stnext = (stnext == 2) ? 0 : stnext + 1;
    }

    #pragma unroll
    for (int mt = 0; mt < 4; mt++) {
        #pragma unroll
        for (int nt = 0; nt < 8; nt++) {
            int row = m0 + wm + mt * 16 + lr;
            int col = n0 + wn + nt * 8 + 2 * lc;
            if (HALF_OUT) {
                __half* C = (__half*)Cv;
                *(uint32_t*)(C + (size_t)row * N + col)       = packh2(c[mt][nt][0], c[mt][nt][1]);
                *(uint32_t*)(C + (size_t)(row + 8) * N + col) = packh2(c[mt][nt][2], c[mt][nt][3]);
            } else {
                float* C = (float*)Cv;
                *(float2*)(C + (size_t)row * N + col)       = make_float2(c[mt][nt][0], c[mt][nt][1]);
                *(float2*)(C + (size_t)(row + 8) * N + col) = make_float2(c[mt][nt][2], c[mt][nt][3]);
            }
        }
    }
}

// ---------------------------------------------------------------------------
// Fused RoPE, vectorized half2. Q pre-scaled by (1/sqrt(d)) * log2(e) so the
// attention softmax can run in base-2 (bare MUFU.EX2, no FMUL).
// ---------------------------------------------------------------------------
__global__ void rope_f16(const __half* __restrict__ QKV,
                         __half* __restrict__ Qh, __half* __restrict__ Kh,
                         __half* __restrict__ Vh)
{
    int idx = blockIdx.x * blockDim.x + threadIdx.x;
    if (idx >= MROWS * N_HEADS * 32) return;
    int j2  = idx & 31;
    int j   = 2 * j2;
    int h   = (idx >> 5) & (N_HEADS - 1);
    int row = idx >> 9;
    int s   = row & (SEQ - 1);

    const float c0 = 13.287712379549449f / 64.0f;
    float sn0, cs0, sn1, cs1;
    sincosf((float)s * exp2f(-(float)j * c0),       &sn0, &cs0);
    sincosf((float)s * exp2f(-(float)(j + 1) * c0), &sn1, &cs1);
    // 1/sqrt(128) * log2(e)
    const float scale = 0.088388347648318447f * 1.4426950408889634f;

    size_t bin  = (size_t)row * NQKV + h * HEAD_DIM + j;
    size_t bout = (size_t)row * D_MODEL + h * HEAD_DIM + j;

    __half2 qlo = *(const __half2*)(QKV + bin);
    __half2 qhi = *(const __half2*)(QKV + bin + 64);
    float2 q1 = __half22float2(qlo), q2 = __half22float2(qhi);
    *(uint32_t*)(Qh + bout)      = packh2((q1.x * cs0 - q2.x * sn0) * scale,
                                          (q1.y * cs1 - q2.y * sn1) * scale);
    *(uint32_t*)(Qh + bout + 64) = packh2((q2.x * cs0 + q1.x * sn0) * scale,
                                          (q2.y * cs1 + q1.y * sn1) * scale);

    __half2 klo = *(const __half2*)(QKV + bin + D_MODEL);
    __half2 khi = *(const __half2*)(QKV + bin + D_MODEL + 64);
    float2 k1 = __half22float2(klo), k2 = __half22float2(khi);
    *(uint32_t*)(Kh + bout)      = packh2(k1.x * cs0 - k2.x * sn0,
                                          k1.y * cs1 - k2.y * sn1);
    *(uint32_t*)(Kh + bout + 64) = packh2(k2.x * cs0 + k1.x * sn0,
                                          k2.y * cs1 + k1.y * sn1);

    *(uint32_t*)(Vh + bout)      = *(const uint32_t*)(QKV + bin + 2 * D_MODEL);
    *(uint32_t*)(Vh + bout + 64) = *(const uint32_t*)(QKV + bin + 2 * D_MODEL + 64);
}

// ---------------------------------------------------------------------------
// Flash attention, fp16 mma, base-2 softmax. 64 q-rows/block, 4 warps, 2 CTA/SM.
// ---------------------------------------------------------------------------
#define QSH 136
#define AQ_ROWS 64
#define OFF_KV (AQ_ROWS*QSH)               // halves
#define KVBUF  (64*QSH)
#define ATTN_SMEM_BYTES ((AQ_ROWS*QSH + 4*KVBUF) * 2)   // 87040

__global__ __launch_bounds__(128, 2) void attn_f16(const __half* __restrict__ Q,
                                                   const __half* __restrict__ K,
                                                   const __half* __restrict__ V,
                                                   __half* __restrict__ O)
{
    extern __shared__ char smraw[];
    const uint32_t sb = s2u(smraw);

    const int tid  = threadIdx.x;
    const int warp = tid >> 5;
    const int lane = tid & 31;
    const int lr = lane >> 2;
    const int lc = lane & 3;
    const int wm = warp * 16;

    const int qx = gridDim.x - 1 - blockIdx.x;   // heavy CTAs first
    const int q0 = qx * AQ_ROWS;
    const int b  = blockIdx.y >> 4;
    const int h  = blockIdx.y & (N_HEADS - 1);

    const __half* Qb = Q + ((size_t)(b * SEQ + q0)) * D_MODEL + h * HEAD_DIM;
    const __half* Kb = K + ((size_t)(b * SEQ)) * D_MODEL + h * HEAD_DIM;
    const __half* Vb = V + ((size_t)(b * SEQ)) * D_MODEL + h * HEAD_DIM;

    const uint32_t aQoff = ((wm + (lane & 15)) * QSH + ((lane & 16) ? 8 : 0)) * 2;
    uint32_t bKoff[4];
    #pragma unroll
    for (int ntp = 0; ntp < 4; ntp++)
        bKoff[ntp] = (((2 * ntp + ((lane & 16) ? 1 : 0)) * 8 + (lane & 7)) * QSH
                      + ((lane & 8) ? 8 : 0)) * 2;
    uint32_t bVoff[8];
    #pragma unroll
    for (int ntp = 0; ntp < 8; ntp++)
        bVoff[ntp] = ((lane & 15) * QSH + (2 * ntp + ((lane & 16) ? 1 : 0)) * 8) * 2;

    {
        #pragma unroll
        for (int i = 0; i < 8; i++) {
            int p = tid + 128 * i;
            int r = p >> 4, ch = p & 15;
            cpa16s(sb + (r * QSH) * 2 + ch * 16, Qb + (size_t)r * D_MODEL + ch * 8);
            cpa16s(sb + (OFF_KV + r * QSH) * 2 + ch * 16,         Kb + (size_t)r * D_MODEL + ch * 8);
            cpa16s(sb + (OFF_KV + KVBUF + r * QSH) * 2 + ch * 16, Vb + (size_t)r * D_MODEL + ch * 8);
        }
        asm volatile("cp.async.commit_group;");
    }

    uint32_t qf[8][4];
    float o_acc[16][4];
    #pragma unroll
    for (int i = 0; i < 16; i++)
        #pragma unroll
        for (int e = 0; e < 4; e++) o_acc[i][e] = 0.f;
    float m0 = -1e30f, m1 = -1e30f, l0 = 0.f, l1 = 0.f;

    const int r0g = q0 + wm + lr;
    const int r1g = r0g + 8;

    const int ntiles = qx + 1;
    for (int kt = 0; kt < ntiles; kt++) {
        asm volatile("cp.async.wait_group 0;");
        __syncthreads();

        if (kt == 0) {
            #pragma unroll
            for (int ks = 0; ks < 8; ks++)
                LDSM_X4(qf[ks][0], qf[ks][1], qf[ks][2], qf[ks][3],
                        sb + aQoff + ks * 32);
        }

        if (kt + 1 < ntiles) {
            const int nb = (kt + 1) & 1;
            const uint32_t dK = sb + (OFF_KV + nb * 2 * KVBUF) * 2;
            const uint32_t dV = dK + KVBUF * 2;
            const size_t krow = (size_t)(kt + 1) * 64;
            #pragma unroll
            for (int i = 0; i < 8; i++) {
                int p = tid + 128 * i;
                int r = p >> 4, ch = p & 15;
                cpa16s(dK + (r * QSH) * 2 + ch * 16, Kb + (krow + r) * D_MODEL + ch * 8);
                cpa16s(dV + (r * QSH) * 2 + ch * 16, Vb + (krow + r) * D_MODEL + ch * 8);
            }
            asm volatile("cp.async.commit_group;");
        }

        const uint32_t bufK = sb + (OFF_KV + (kt & 1) * 2 * KVBUF) * 2;
        const uint32_t bufV = bufK + KVBUF * 2;
        const int k0 = kt * 64;

        float s[8][4];
        #pragma unroll
        for (int nt = 0; nt < 8; nt++)
            #pragma unroll
            for (int e = 0; e < 4; e++) s[nt][e] = 0.f;

        #pragma unroll
        for (int ks = 0; ks < 8; ks++) {
            #pragma unroll
            for (int ntp = 0; ntp < 4; ntp++) {
                uint32_t b0, b1, b2, b3;
                LDSM_X4(b0, b1, b2, b3, bufK + bKoff[ntp] + ks * 32);
                mma_f16(s[2 * ntp],     qf[ks][0], qf[ks][1], qf[ks][2], qf[ks][3], b0, b1);
                mma_f16(s[2 * ntp + 1], qf[ks][0], qf[ks][1], qf[ks][2], qf[ks][3], b2, b3);
            }
        }

        float rm0 = -1e30f, rm1 = -1e30f;
        #pragma unroll
        for (int nt = 0; nt < 8; nt++) {
            int c0 = k0 + nt * 8 + 2 * lc;
            if (c0     > r0g) s[nt][0] = -1e30f;
            if (c0 + 1 > r0g) s[nt][1] = -1e30f;
            if (c0     > r1g) s[nt][2] = -1e30f;
            if (c0 + 1 > r1g) s[nt][3] = -1e30f;
            rm0 = fmaxf(rm0, fmaxf(s[nt][0], s[nt][1]));
            rm1 = fmaxf(rm1, fmaxf(s[nt][2], s[nt][3]));
        }
        rm0 = fmaxf(rm0, __shfl_xor_sync(0xffffffffu, rm0, 1));
        rm0 = fmaxf(rm0, __shfl_xor_sync(0xffffffffu, rm0, 2));
        rm1 = fmaxf(rm1, __shfl_xor_sync(0xffffffffu, rm1, 1));
        rm1 = fmaxf(rm1, __shfl_xor_sync(0xffffffffu, rm1, 2));

        float mn0 = fmaxf(m0, rm0), mn1 = fmaxf(m1, rm1);
        float al0 = exp2f(m0 - mn0), al1 = exp2f(m1 - mn1);
        m0 = mn0; m1 = mn1;

        float ps0 = 0.f, ps1 = 0.f;
        uint32_t pa[8], pb[8];
        #pragma unroll
        for (int nt = 0; nt < 8; nt++) {
            float p00 = exp2f(s[nt][0] - mn0);
            float p01 = exp2f(s[nt][1] - mn0);
            float p10 = exp2f(s[nt][2] - mn1);
            float p11 = exp2f(s[nt][3] - mn1);
            ps0 += p00 + p01;
            ps1 += p10 + p11;
            pa[nt] = packh2(p00, p01);
            pb[nt] = packh2(p10, p11);
        }
        ps0 += __shfl_xor_sync(0xffffffffu, ps0, 1);
        ps0 += __shfl_xor_sync(0xffffffffu, ps0, 2);
        ps1 += __shfl_xor_sync(0xffffffffu, ps1, 1);
        ps1 += __shfl_xor_sync(0xffffffffu, ps1, 2);
        l0 = l0 * al0 + ps0;
        l1 = l1 * al1 + ps1;

        #pragma unroll
        for (int nt2 = 0; nt2 < 16; nt2++) {
            o_acc[nt2][0] *= al0; o_acc[nt2][1] *= al0;
            o_acc[nt2][2] *= al1; o_acc[nt2][3] *= al1;
        }

        #pragma unroll
        for (int j = 0; j < 4; j++) {
            uint32_t a0 = pa[2 * j],     a1 = pb[2 * j];
            uint32_t a2 = pa[2 * j + 1], a3 = pb[2 * j + 1];
            #pragma unroll
            for (int ntp = 0; ntp < 8; ntp++) {
                uint32_t b0, b1, b2, b3;
                LDSM_X4T(b0, b1, b2, b3, bufV + bVoff[ntp] + j * 16 * QSH * 2);
                mma_f16(o_acc[2 * ntp],     a0, a1, a2, a3, b0, b1);
                mma_f16(o_acc[2 * ntp + 1], a0, a1, a2, a3, b2, b3);
            }
        }
    }

    float inv0 = 1.0f / l0, inv1 = 1.0f / l1;
    __half* Ob = O + ((size_t)(b * SEQ + q0 + wm + lr)) * D_MODEL + h * HEAD_DIM;
    #pragma unroll
    for (int nt2 = 0; nt2 < 16; nt2++) {
        int col = nt2 * 8 + 2 * lc;
        *(uint32_t*)(Ob + col)               = packh2(o_acc[nt2][0] * inv0, o_acc[nt2][1] * inv0);
        *(uint32_t*)(Ob + 8 * D_MODEL + col) = packh2(o_acc[nt2][2] * inv1, o_acc[nt2][3] * inv1);
    }
}

// ---------------------------------------------------------------------------
extern "C" void kernel_launch(void* const* d_in, const int* in_sizes, int n_in,
                              void* d_out, int out_size)
{
    const float* X  = (const float*)d_in[0];
    const float* Wq = (const float*)d_in[1];
    const float* Wk = (const float*)d_in[2];
    const float* Wv = (const float*)d_in[3];
    const float* Wo = (const float*)d_in[4];
    float* out = (float*)d_out;

    __half *qkvh, *qh, *kh, *vh, *xh, *oh, *wh;
    cudaGetSymbolAddress((void**)&qkvh, g_qkvh);
    cudaGetSymbolAddress((void**)&qh, g_qh);
    cudaGetSymbolAddress((void**)&kh, g_kh);
    cudaGetSymbolAddress((void**)&vh, g_vh);
    cudaGetSymbolAddress((void**)&xh, g_xh);
    cudaGetSymbolAddress((void**)&oh, g_oh);
    cudaGetSymbolAddress((void**)&wh, g_wh);
    __half* woh = wh + 3 * (size_t)D_MODEL * D_MODEL;

    cudaFuncSetAttribute(attn_f16, cudaFuncAttributeMaxDynamicSharedMemorySize,
                         ATTN_SMEM_BYTES);
    cudaFuncSetAttribute(gemm_f16<true>, cudaFuncAttributeMaxDynamicSharedMemorySize,
                         GEMMH_SMEM);
    cudaFuncSetAttribute(gemm_f16<false>, cudaFuncAttributeMaxDynamicSharedMemorySize,
                         GEMMH_SMEM);

    // 1) fp16 conversion of all operands, single launch
    {
        int ntot = NX4 + 4 * NW4;
        f2h_all<<<(ntot + 255) / 256, 256>>>(
            (const float4*)X, (const float4*)Wq, (const float4*)Wk,
            (const float4*)Wv, (const float4*)Wo, (uint2*)xh, (uint2*)wh);
    }

    // 2) fused QKV projection (R11 proven config)
    gemm_f16<true><<<dim3(NQKV / 128, MROWS / HBM), 128, GEMMH_SMEM>>>(
        xh, wh, qkvh, MROWS, NQKV, D_MODEL);

    // 3) fused RoPE (+ Q pre-scale incl. log2e)
    rope_f16<<<(MROWS * N_HEADS * 32) / 256, 256>>>(qkvh, qh, kh, vh);

    // 4) attention (base-2 softmax, 2 CTAs/SM)
    attn_f16<<<dim3(SEQ / AQ_ROWS, BATCH * N_HEADS), 128, ATTN_SMEM_BYTES>>>(qh, kh, vh, oh);

    // 5) output projection (fp32 out)
    gemm_f16<false><<<dim3(D_MODEL / 128, MROWS / HBM), 128, GEMMH_SMEM>>>(
        oh, woh, out, MROWS, D_MODEL, D_MODEL);
}

// round 16
// speedup vs baseline: 1.0471x; 1.0311x over previous
#include <cuda_runtime.h>
#include <cuda_fp16.h>
#include <math.h>
#include <stdint.h>

#define D_MODEL 2048
#define N_HEADS 16
#define HEAD_DIM 128
#define SEQ 2048
#define BATCH 2
#define MROWS (BATCH*SEQ)   // 4096
#define NQKV (3*D_MODEL)    // 6144

// Scratch (static device globals; no allocation allowed)
__device__ __half g_qkvh[(size_t)MROWS * NQKV];
__device__ __half g_xh[(size_t)MROWS * D_MODEL];
__device__ __half g_oh[(size_t)MROWS * D_MODEL];
__device__ __half g_wh[4][(size_t)D_MODEL * D_MODEL];

// ---------------------------------------------------------------------------
// helpers
// ---------------------------------------------------------------------------
#define NX4 ((MROWS * D_MODEL) / 4)
#define NW4 ((D_MODEL * D_MODEL) / 4)

__global__ void f2h_all(const float4* __restrict__ X,
                        const float4* __restrict__ Wq, const float4* __restrict__ Wk,
                        const float4* __restrict__ Wv, const float4* __restrict__ Wo,
                        uint2* __restrict__ xh, uint2* __restrict__ wh)
{
    int i = blockIdx.x * blockDim.x + threadIdx.x;
    const float4* src;
    uint2* dst;
    if (i < NX4) {
        src = X + i; dst = xh + i;
    } else {
        int j = i - NX4;
        int r = j / NW4;
        int o = j - r * NW4;
        const float4* ws[4] = {Wq, Wk, Wv, Wo};
        src = ws[r] + o;
        dst = wh + (size_t)r * NW4 + o;
    }
    float4 v = *src;
    __half2 h01 = __floats2half2_rn(v.x, v.y);
    __half2 h23 = __floats2half2_rn(v.z, v.w);
    *dst = make_uint2(*(uint32_t*)&h01, *(uint32_t*)&h23);
}

__device__ __forceinline__ void cpa16s(uint32_t saddr, const void* g) {
    asm volatile("cp.async.cg.shared.global [%0], [%1], 16;" :: "r"(saddr), "l"(g));
}

__device__ __forceinline__ uint32_t s2u(const void* p) {
    uint32_t a;
    asm("{ .reg .u64 t; cvta.to.shared.u64 t, %1; cvt.u32.u64 %0, t; }" : "=r"(a) : "l"(p));
    return a;
}

__device__ __forceinline__ void mma_f16(float* c,
                                        uint32_t a0, uint32_t a1, uint32_t a2, uint32_t a3,
                                        uint32_t b0, uint32_t b1)
{
    asm volatile(
        "mma.sync.aligned.m16n8k16.row.col.f32.f16.f16.f32 "
        "{%0,%1,%2,%3},{%4,%5,%6,%7},{%8,%9},{%0,%1,%2,%3};"
        : "+f"(c[0]), "+f"(c[1]), "+f"(c[2]), "+f"(c[3])
        : "r"(a0), "r"(a1), "r"(a2), "r"(a3), "r"(b0), "r"(b1));
}

#define LDSM_X4(R0,R1,R2,R3,ADDR) \
    asm volatile("ldmatrix.sync.aligned.m8n8.x4.shared.b16 {%0,%1,%2,%3}, [%4];" \
        : "=r"(R0), "=r"(R1), "=r"(R2), "=r"(R3) : "r"(ADDR))

#define LDSM_X4T(R0,R1,R2,R3,ADDR) \
    asm volatile("ldmatrix.sync.aligned.m8n8.x4.trans.shared.b16 {%0,%1,%2,%3}, [%4];" \
        : "=r"(R0), "=r"(R1), "=r"(R2), "=r"(R3) : "r"(ADDR))

__device__ __forceinline__ uint32_t packh2(float a, float b) {
    __half2 h = __floats2half2_rn(a, b);
    return *(uint32_t*)&h;
}

#define HROWB 144

// ---------------------------------------------------------------------------
// fp16 GEMM NT 128x128, 4 warps (64x64), 3-stage cp.async, 2 CTA/SM. (R11)
// ---------------------------------------------------------------------------
#define HBM 128
#define HBK 64
#define STAGE_BYTES (2 * HBM * HROWB)
#define GEMMH_SMEM (3 * STAGE_BYTES)      // 110592 bytes

template<bool HALF_OUT>
__global__ __launch_bounds__(128, 2) void gemm_f16(const __half* __restrict__ A,
                                                   const __half* __restrict__ B,
                                                   void* __restrict__ Cv,
                                                   int M, int N, int K)
{
    extern __shared__ char smraw[];
    const uint32_t sb = s2u(smraw);

    const int tid  = threadIdx.x;
    const int warp = tid >> 5;
    const int lane = tid & 31;
    const int wm = (warp >> 1) * 64;
    const int wn = (warp & 1) * 64;
    const int lr = lane >> 2;
    const int lc = lane & 3;

    const int m0 = blockIdx.y * HBM;
    const int n0 = blockIdx.x * 128;

    const int ldr  = tid >> 3;
    const int ldch = (tid & 7) * 16;

    const char* Ab = (const char*)(A + (size_t)m0 * K);
    const char* Bb = (const char*)(B + (size_t)n0 * K);

    uint32_t aOff[4], bOff[4];
    #pragma unroll
    for (int mt = 0; mt < 4; mt++)
        aOff[mt] = (wm + mt * 16 + (lane & 15)) * HROWB + ((lane & 16) ? 16 : 0);
    #pragma unroll
    for (int ntp = 0; ntp < 4; ntp++)
        bOff[ntp] = HBM * HROWB
                  + (wn + (2 * ntp + ((lane & 16) ? 1 : 0)) * 8 + (lane & 7)) * HROWB
                  + ((lane & 8) ? 16 : 0);

    float c[4][8][4];
    #pragma unroll
    for (int i = 0; i < 4; i++)
        #pragma unroll
        for (int j = 0; j < 8; j++)
            #pragma unroll
            for (int e = 0; e < 4; e++) c[i][j][e] = 0.f;

    const int nk = K / HBK;

    #pragma unroll
    for (int st = 0; st < 2; st++) {
        const size_t kb = (size_t)st * HBK * 2;
        const uint32_t dA = sb + st * STAGE_BYTES;
        const uint32_t dB = dA + HBM * HROWB;
        #pragma unroll
        for (int i = 0; i < 8; i++) {
            int r = ldr + 16 * i;
            cpa16s(dA + r * HROWB + ldch, Ab + (size_t)r * K * 2 + kb + ldch);
            cpa16s(dB + r * HROWB + ldch, Bb + (size_t)r * K * 2 + kb + ldch);
        }
        asm volatile("cp.async.commit_group;");
    }

    int stcur = 0, stnext = 2;
    for (int kt = 0; kt < nk; kt++) {
        if (kt + 2 < nk)
            asm volatile("cp.async.wait_group 1;");
        else
            asm volatile("cp.async.wait_group 0;");
        __syncthreads();

        if (kt + 2 < nk) {
            const size_t kb = (size_t)(kt + 2) * HBK * 2;
            const uint32_t dA = sb + stnext * STAGE_BYTES;
            const uint32_t dB = dA + HBM * HROWB;
            #pragma unroll
            for (int i = 0; i < 8; i++) {
                int r = ldr + 16 * i;
                cpa16s(dA + r * HROWB + ldch, Ab + (size_t)r * K * 2 + kb + ldch);
                cpa16s(dB + r * HROWB + ldch, Bb + (size_t)r * K * 2 + kb + ldch);
            }
            asm volatile("cp.async.commit_group;");
        }

        const uint32_t buf = sb + stcur * STAGE_BYTES;

        #pragma unroll
        for (int ks = 0; ks < 4; ks++) {
            uint32_t a[4][4], b[4][4];
            #pragma unroll
            for (int mt = 0; mt < 4; mt++)
                LDSM_X4(a[mt][0], a[mt][1], a[mt][2], a[mt][3],
                        buf + aOff[mt] + ks * 32);
            #pragma unroll
            for (int ntp = 0; ntp < 4; ntp++)
                LDSM_X4(b[ntp][0], b[ntp][1], b[ntp][2], b[ntp][3],
                        buf + bOff[ntp] + ks * 32);
            #pragma unroll
            for (int mt = 0; mt < 4; mt++)
                #pragma unroll
                for (int nt = 0; nt < 8; nt++)
                    mma_f16(c[mt][nt], a[mt][0], a[mt][1], a[mt][2], a[mt][3],
                            b[nt >> 1][(nt & 1) * 2], b[nt >> 1][(nt & 1) * 2 + 1]);
        }

        stcur  = (stcur == 2)  ? 0 : stcur + 1;
        stnext = (stnext == 2) ? 0 : stnext + 1;
    }

    #pragma unroll
    for (int mt = 0; mt < 4; mt++) {
        #pragma unroll
        for (int nt = 0; nt < 8; nt++) {
            int row = m0 + wm + mt * 16 + lr;
            int col = n0 + wn + nt * 8 + 2 * lc;
            if (HALF_OUT) {
                __half* C = (__half*)Cv;
                *(uint32_t*)(C + (size_t)row * N + col)       = packh2(c[mt][nt][0], c[mt][nt][1]);
                *(uint32_t*)(C + (size_t)(row + 8) * N + col) = packh2(c[mt][nt][2], c[mt][nt][3]);
            } else {
                float* C = (float*)Cv;
                *(float2*)(C + (size_t)row * N + col)       = make_float2(c[mt][nt][0], c[mt][nt][1]);
                *(float2*)(C + (size_t)(row + 8) * N + col) = make_float2(c[mt][nt][2], c[mt][nt][3]);
            }
        }
    }
}

// ---------------------------------------------------------------------------
// Fused RoPE, IN PLACE on qkvh (Q and K regions; V untouched).
// Q pre-scaled by (1/sqrt(d)) * log2(e) for base-2 softmax.
// ---------------------------------------------------------------------------
__global__ void rope_f16(__half* __restrict__ QKV)
{
    int idx = blockIdx.x * blockDim.x + threadIdx.x;
    if (idx >= MROWS * N_HEADS * 32) return;
    int j2  = idx & 31;
    int j   = 2 * j2;
    int h   = (idx >> 5) & (N_HEADS - 1);
    int row = idx >> 9;
    int s   = row & (SEQ - 1);

    const float c0 = 13.287712379549449f / 64.0f;
    float sn0, cs0, sn1, cs1;
    sincosf((float)s * exp2f(-(float)j * c0),       &sn0, &cs0);
    sincosf((float)s * exp2f(-(float)(j + 1) * c0), &sn1, &cs1);
    // 1/sqrt(128) * log2(e)
    const float scale = 0.088388347648318447f * 1.4426950408889634f;

    size_t bin = (size_t)row * NQKV + h * HEAD_DIM + j;

    __half2 qlo = *(const __half2*)(QKV + bin);
    __half2 qhi = *(const __half2*)(QKV + bin + 64);
    float2 q1 = __half22float2(qlo), q2 = __half22float2(qhi);
    *(uint32_t*)(QKV + bin)      = packh2((q1.x * cs0 - q2.x * sn0) * scale,
                                          (q1.y * cs1 - q2.y * sn1) * scale);
    *(uint32_t*)(QKV + bin + 64) = packh2((q2.x * cs0 + q1.x * sn0) * scale,
                                          (q2.y * cs1 + q1.y * sn1) * scale);

    __half2 klo = *(const __half2*)(QKV + bin + D_MODEL);
    __half2 khi = *(const __half2*)(QKV + bin + D_MODEL + 64);
    float2 k1 = __half22float2(klo), k2 = __half22float2(khi);
    *(uint32_t*)(QKV + bin + D_MODEL)      = packh2(k1.x * cs0 - k2.x * sn0,
                                                    k1.y * cs1 - k2.y * sn1);
    *(uint32_t*)(QKV + bin + D_MODEL + 64) = packh2(k2.x * cs0 + k1.x * sn0,
                                                    k2.y * cs1 + k1.y * sn1);
}

// ---------------------------------------------------------------------------
// Flash attention, fp16 mma, base-2 softmax, reads strided fused qkvh.
// 64 q-rows/block, 4 warps, 2 CTA/SM. Mask applied only on diagonal tile.
// ---------------------------------------------------------------------------
#define QSH 136
#define AQ_ROWS 64
#define OFF_KV (AQ_ROWS*QSH)               // halves
#define KVBUF  (64*QSH)
#define ATTN_SMEM_BYTES ((AQ_ROWS*QSH + 4*KVBUF) * 2)   // 87040

__global__ __launch_bounds__(128, 2) void attn_f16(const __half* __restrict__ QKV,
                                                   __half* __restrict__ O)
{
    extern __shared__ char smraw[];
    const uint32_t sb = s2u(smraw);

    const int tid  = threadIdx.x;
    const int warp = tid >> 5;
    const int lane = tid & 31;
    const int lr = lane >> 2;
    const int lc = lane & 3;
    const int wm = warp * 16;

    const int qx = gridDim.x - 1 - blockIdx.x;   // heavy CTAs first
    const int q0 = qx * AQ_ROWS;
    const int b  = blockIdx.y >> 4;
    const int h  = blockIdx.y & (N_HEADS - 1);

    const __half* Qb = QKV + ((size_t)(b * SEQ + q0)) * NQKV + h * HEAD_DIM;
    const __half* Kb = QKV + ((size_t)(b * SEQ)) * NQKV + D_MODEL + h * HEAD_DIM;
    const __half* Vb = QKV + ((size_t)(b * SEQ)) * NQKV + 2 * D_MODEL + h * HEAD_DIM;

    const uint32_t aQoff = ((wm + (lane & 15)) * QSH + ((lane & 16) ? 8 : 0)) * 2;
    uint32_t bKoff[4];
    #pragma unroll
    for (int ntp = 0; ntp < 4; ntp++)
        bKoff[ntp] = (((2 * ntp + ((lane & 16) ? 1 : 0)) * 8 + (lane & 7)) * QSH
                      + ((lane & 8) ? 8 : 0)) * 2;
    uint32_t bVoff[8];
    #pragma unroll
    for (int ntp = 0; ntp < 8; ntp++)
        bVoff[ntp] = ((lane & 15) * QSH + (2 * ntp + ((lane & 16) ? 1 : 0)) * 8) * 2;

    {
        #pragma unroll
        for (int i = 0; i < 8; i++) {
            int p = tid + 128 * i;
            int r = p >> 4, ch = p & 15;
            cpa16s(sb + (r * QSH) * 2 + ch * 16, Qb + (size_t)r * NQKV + ch * 8);
            cpa16s(sb + (OFF_KV + r * QSH) * 2 + ch * 16,         Kb + (size_t)r * NQKV + ch * 8);
            cpa16s(sb + (OFF_KV + KVBUF + r * QSH) * 2 + ch * 16, Vb + (size_t)r * NQKV + ch * 8);
        }
        asm volatile("cp.async.commit_group;");
    }

    uint32_t qf[8][4];
    float o_acc[16][4];
    #pragma unroll
    for (int i = 0; i < 16; i++)
        #pragma unroll
        for (int e = 0; e < 4; e++) o_acc[i][e] = 0.f;
    float m0 = -1e30f, m1 = -1e30f, l0 = 0.f, l1 = 0.f;

    const int r0g = q0 + wm + lr;
    const int r1g = r0g + 8;

    const int ntiles = qx + 1;
    for (int kt = 0; kt < ntiles; kt++) {
        asm volatile("cp.async.wait_group 0;");
        __syncthreads();

        if (kt == 0) {
            #pragma unroll
            for (int ks = 0; ks < 8; ks++)
                LDSM_X4(qf[ks][0], qf[ks][1], qf[ks][2], qf[ks][3],
                        sb + aQoff + ks * 32);
        }

        if (kt + 1 < ntiles) {
            const int nb = (kt + 1) & 1;
            const uint32_t dK = sb + (OFF_KV + nb * 2 * KVBUF) * 2;
            const uint32_t dV = dK + KVBUF * 2;
            const size_t krow = (size_t)(kt + 1) * 64;
            #pragma unroll
            for (int i = 0; i < 8; i++) {
                int p = tid + 128 * i;
                int r = p >> 4, ch = p & 15;
                cpa16s(dK + (r * QSH) * 2 + ch * 16, Kb + (krow + r) * NQKV + ch * 8);
                cpa16s(dV + (r * QSH) * 2 + ch * 16, Vb + (krow + r) * NQKV + ch * 8);
            }
            asm volatile("cp.async.commit_group;");
        }

        const uint32_t bufK = sb + (OFF_KV + (kt & 1) * 2 * KVBUF) * 2;
        const uint32_t bufV = bufK + KVBUF * 2;
        const int k0 = kt * 64;

        float s[8][4];
        #pragma unroll
        for (int nt = 0; nt < 8; nt++)
            #pragma unroll
            for (int e = 0; e < 4; e++) s[nt][e] = 0.f;

        #pragma unroll
        for (int ks = 0; ks < 8; ks++) {
            #pragma unroll
            for (int ntp = 0; ntp < 4; ntp++) {
                uint32_t b0, b1, b2, b3;
                LDSM_X4(b0, b1, b2, b3, bufK + bKoff[ntp] + ks * 32);
                mma_f16(s[2 * ntp],     qf[ks][0], qf[ks][1], qf[ks][2], qf[ks][3], b0, b1);
                mma_f16(s[2 * ntp + 1], qf[ks][0], qf[ks][1], qf[ks][2], qf[ks][3], b2, b3);
            }
        }

        // causal mask: only the diagonal tile needs it
        if (kt == ntiles - 1) {
            #pragma unroll
            for (int nt = 0; nt < 8; nt++) {
                int c0 = k0 + nt * 8 + 2 * lc;
                if (c0     > r0g) s[nt][0] = -1e30f;
                if (c0 + 1 > r0g) s[nt][1] = -1e30f;
                if (c0     > r1g) s[nt][2] = -1e30f;
                if (c0 + 1 > r1g) s[nt][3] = -1e30f;
            }
        }

        float rm0 = -1e30f, rm1 = -1e30f;
        #pragma unroll
        for (int nt = 0; nt < 8; nt++) {
            rm0 = fmaxf(rm0, fmaxf(s[nt][0], s[nt][1]));
            rm1 = fmaxf(rm1, fmaxf(s[nt][2], s[nt][3]));
        }
        rm0 = fmaxf(rm0, __shfl_xor_sync(0xffffffffu, rm0, 1));
        rm0 = fmaxf(rm0, __shfl_xor_sync(0xffffffffu, rm0, 2));
        rm1 = fmaxf(rm1, __shfl_xor_sync(0xffffffffu, rm1, 1));
        rm1 = fmaxf(rm1, __shfl_xor_sync(0xffffffffu, rm1, 2));

        float mn0 = fmaxf(m0, rm0), mn1 = fmaxf(m1, rm1);
        float al0 = exp2f(m0 - mn0), al1 = exp2f(m1 - mn1);
        m0 = mn0; m1 = mn1;

        float ps0 = 0.f, ps1 = 0.f;
        uint32_t pa[8], pb[8];
        #pragma unroll
        for (int nt = 0; nt < 8; nt++) {
            float p00 = exp2f(s[nt][0] - mn0);
            float p01 = exp2f(s[nt][1] - mn0);
            float p10 = exp2f(s[nt][2] - mn1);
            float p11 = exp2f(s[nt][3] - mn1);
            ps0 += p00 + p01;
            ps1 += p10 + p11;
            pa[nt] = packh2(p00, p01);
            pb[nt] = packh2(p10, p11);
        }
        ps0 += __shfl_xor_sync(0xffffffffu, ps0, 1);
        ps0 += __shfl_xor_sync(0xffffffffu, ps0, 2);
        ps1 += __shfl_xor_sync(0xffffffffu, ps1, 1);
        ps1 += __shfl_xor_sync(0xffffffffu, ps1, 2);
        l0 = l0 * al0 + ps0;
        l1 = l1 * al1 + ps1;

        #pragma unroll
        for (int nt2 = 0; nt2 < 16; nt2++) {
            o_acc[nt2][0] *= al0; o_acc[nt2][1] *= al0;
            o_acc[nt2][2] *= al1; o_acc[nt2][3] *= al1;
        }

        #pragma unroll
        for (int j = 0; j < 4; j++) {
            uint32_t a0 = pa[2 * j],     a1 = pb[2 * j];
            uint32_t a2 = pa[2 * j + 1], a3 = pb[2 * j + 1];
            #pragma unroll
            for (int ntp = 0; ntp < 8; ntp++) {
                uint32_t b0, b1, b2, b3;
                LDSM_X4T(b0, b1, b2, b3, bufV + bVoff[ntp] + j * 16 * QSH * 2);
                mma_f16(o_acc[2 * ntp],     a0, a1, a2, a3, b0, b1);
                mma_f16(o_acc[2 * ntp + 1], a0, a1, a2, a3, b2, b3);
            }
        }
    }

    float inv0 = 1.0f / l0, inv1 = 1.0f / l1;
    __half* Ob = O + ((size_t)(b * SEQ + q0 + wm + lr)) * D_MODEL + h * HEAD_DIM;
    #pragma unroll
    for (int nt2 = 0; nt2 < 16; nt2++) {
        int col = nt2 * 8 + 2 * lc;
        *(uint32_t*)(Ob + col)               = packh2(o_acc[nt2][0] * inv0, o_acc[nt2][1] * inv0);
        *(uint32_t*)(Ob + 8 * D_MODEL + col) = packh2(o_acc[nt2][2] * inv1, o_acc[nt2][3] * inv1);
    }
}

// ---------------------------------------------------------------------------
extern "C" void kernel_launch(void* const* d_in, const int* in_sizes, int n_in,
                              void* d_out, int out_size)
{
    const float* X  = (const float*)d_in[0];
    const float* Wq = (const float*)d_in[1];
    const float* Wk = (const float*)d_in[2];
    const float* Wv = (const float*)d_in[3];
    const float* Wo = (const float*)d_in[4];
    float* out = (float*)d_out;

    __half *qkvh, *xh, *oh, *wh;
    cudaGetSymbolAddress((void**)&qkvh, g_qkvh);
    cudaGetSymbolAddress((void**)&xh, g_xh);
    cudaGetSymbolAddress((void**)&oh, g_oh);
    cudaGetSymbolAddress((void**)&wh, g_wh);
    __half* woh = wh + 3 * (size_t)D_MODEL * D_MODEL;

    cudaFuncSetAttribute(attn_f16, cudaFuncAttributeMaxDynamicSharedMemorySize,
                         ATTN_SMEM_BYTES);
    cudaFuncSetAttribute(gemm_f16<true>, cudaFuncAttributeMaxDynamicSharedMemorySize,
                         GEMMH_SMEM);
    cudaFuncSetAttribute(gemm_f16<false>, cudaFuncAttributeMaxDynamicSharedMemorySize,
                         GEMMH_SMEM);

    // 1) fp16 conversion of all operands, single launch
    {
        int ntot = NX4 + 4 * NW4;
        f2h_all<<<(ntot + 255) / 256, 256>>>(
            (const float4*)X, (const float4*)Wq, (const float4*)Wk,
            (const float4*)Wv, (const float4*)Wo, (uint2*)xh, (uint2*)wh);
    }

    // 2) fused QKV projection
    gemm_f16<true><<<dim3(NQKV / 128, MROWS / HBM), 128, GEMMH_SMEM>>>(
        xh, wh, qkvh, MROWS, NQKV, D_MODEL);

    // 3) fused RoPE in place on qkvh (Q pre-scale incl. log2e)
    rope_f16<<<(MROWS * N_HEADS * 32) / 256, 256>>>(qkvh);

    // 4) attention (reads strided qkvh; base-2 softmax; 2 CTAs/SM)
    attn_f16<<<dim3(SEQ / AQ_ROWS, BATCH * N_HEADS), 128, ATTN_SMEM_BYTES>>>(qkvh, oh);

    // 5) output projection (fp32 out)
    gemm_f16<false><<<dim3(D_MODEL / 128, MROWS / HBM), 128, GEMMH_SMEM>>>(
        oh, woh, out, MROWS, D_MODEL, D_MODEL);
}

// round 17
// speedup vs baseline: 1.0514x; 1.0041x over previous
#include <cuda_runtime.h>
#include <cuda_fp16.h>
#include <math.h>
#include <stdint.h>

#define D_MODEL 2048
#define N_HEADS 16
#define HEAD_DIM 128
#define SEQ 2048
#define BATCH 2
#define MROWS (BATCH*SEQ)   // 4096
#define NQKV (3*D_MODEL)    // 6144

// Scratch (static device globals; no allocation allowed)
__device__ __half g_qkvh[(size_t)MROWS * NQKV];
__device__ __half g_xh[(size_t)MROWS * D_MODEL];
__device__ __half g_oh[(size_t)MROWS * D_MODEL];
__device__ __half g_wh[4][(size_t)D_MODEL * D_MODEL];

// ---------------------------------------------------------------------------
// helpers
// ---------------------------------------------------------------------------
#define NX4 ((MROWS * D_MODEL) / 4)
#define NW4 ((D_MODEL * D_MODEL) / 4)

__global__ void f2h_all(const float4* __restrict__ X,
                        const float4* __restrict__ Wq, const float4* __restrict__ Wk,
                        const float4* __restrict__ Wv, const float4* __restrict__ Wo,
                        uint2* __restrict__ xh, uint2* __restrict__ wh)
{
    int i = blockIdx.x * blockDim.x + threadIdx.x;
    const float4* src;
    uint2* dst;
    if (i < NX4) {
        src = X + i; dst = xh + i;
    } else {
        int j = i - NX4;
        int r = j / NW4;
        int o = j - r * NW4;
        const float4* ws[4] = {Wq, Wk, Wv, Wo};
        src = ws[r] + o;
        dst = wh + (size_t)r * NW4 + o;
    }
    float4 v = *src;
    __half2 h01 = __floats2half2_rn(v.x, v.y);
    __half2 h23 = __floats2half2_rn(v.z, v.w);
    *dst = make_uint2(*(uint32_t*)&h01, *(uint32_t*)&h23);
}

__device__ __forceinline__ void cpa16s(uint32_t saddr, const void* g) {
    asm volatile("cp.async.cg.shared.global [%0], [%1], 16;" :: "r"(saddr), "l"(g));
}

__device__ __forceinline__ uint32_t s2u(const void* p) {
    uint32_t a;
    asm("{ .reg .u64 t; cvta.to.shared.u64 t, %1; cvt.u32.u64 %0, t; }" : "=r"(a) : "l"(p));
    return a;
}

__device__ __forceinline__ void mma_f16(float* c,
                                        uint32_t a0, uint32_t a1, uint32_t a2, uint32_t a3,
                                        uint32_t b0, uint32_t b1)
{
    asm volatile(
        "mma.sync.aligned.m16n8k16.row.col.f32.f16.f16.f32 "
        "{%0,%1,%2,%3},{%4,%5,%6,%7},{%8,%9},{%0,%1,%2,%3};"
        : "+f"(c[0]), "+f"(c[1]), "+f"(c[2]), "+f"(c[3])
        : "r"(a0), "r"(a1), "r"(a2), "r"(a3), "r"(b0), "r"(b1));
}

#define LDSM_X4(R0,R1,R2,R3,ADDR) \
    asm volatile("ldmatrix.sync.aligned.m8n8.x4.shared.b16 {%0,%1,%2,%3}, [%4];" \
        : "=r"(R0), "=r"(R1), "=r"(R2), "=r"(R3) : "r"(ADDR))

#define LDSM_X4T(R0,R1,R2,R3,ADDR) \
    asm volatile("ldmatrix.sync.aligned.m8n8.x4.trans.shared.b16 {%0,%1,%2,%3}, [%4];" \
        : "=r"(R0), "=r"(R1), "=r"(R2), "=r"(R3) : "r"(ADDR))

__device__ __forceinline__ uint32_t packh2(float a, float b) {
    __half2 h = __floats2half2_rn(a, b);
    return *(uint32_t*)&h;
}

#define HROWB 144

// ---------------------------------------------------------------------------
// fp16 GEMM NT 128x128, 4 warps (64x64), 3-stage cp.async, 2 CTA/SM. (R11)
// ---------------------------------------------------------------------------
#define HBM 128
#define HBK 64
#define STAGE_BYTES (2 * HBM * HROWB)
#define GEMMH_SMEM (3 * STAGE_BYTES)      // 110592 bytes

template<bool HALF_OUT>
__global__ __launch_bounds__(128, 2) void gemm_f16(const __half* __restrict__ A,
                                                   const __half* __restrict__ B,
                                                   void* __restrict__ Cv,
                                                   int M, int N, int K)
{
    extern __shared__ char smraw[];
    const uint32_t sb = s2u(smraw);

    const int tid  = threadIdx.x;
    const int warp = tid >> 5;
    const int lane = tid & 31;
    const int wm = (warp >> 1) * 64;
    const int wn = (warp & 1) * 64;
    const int lr = lane >> 2;
    const int lc = lane & 3;

    const int m0 = blockIdx.y * HBM;
    const int n0 = blockIdx.x * 128;

    const int ldr  = tid >> 3;
    const int ldch = (tid & 7) * 16;

    const char* Ab = (const char*)(A + (size_t)m0 * K);
    const char* Bb = (const char*)(B + (size_t)n0 * K);

    uint32_t aOff[4], bOff[4];
    #pragma unroll
    for (int mt = 0; mt < 4; mt++)
        aOff[mt] = (wm + mt * 16 + (lane & 15)) * HROWB + ((lane & 16) ? 16 : 0);
    #pragma unroll
    for (int ntp = 0; ntp < 4; ntp++)
        bOff[ntp] = HBM * HROWB
                  + (wn + (2 * ntp + ((lane & 16) ? 1 : 0)) * 8 + (lane & 7)) * HROWB
                  + ((lane & 8) ? 16 : 0);

    float c[4][8][4];
    #pragma unroll
    for (int i = 0; i < 4; i++)
        #pragma unroll
        for (int j = 0; j < 8; j++)
            #pragma unroll
            for (int e = 0; e < 4; e++) c[i][j][e] = 0.f;

    const int nk = K / HBK;

    #pragma unroll
    for (int st = 0; st < 2; st++) {
        const size_t kb = (size_t)st * HBK * 2;
        const uint32_t dA = sb + st * STAGE_BYTES;
        const uint32_t dB = dA + HBM * HROWB;
        #pragma unroll
        for (int i = 0; i < 8; i++) {
            int r = ldr + 16 * i;
            cpa16s(dA + r * HROWB + ldch, Ab + (size_t)r * K * 2 + kb + ldch);
            cpa16s(dB + r * HROWB + ldch, Bb + (size_t)r * K * 2 + kb + ldch);
        }
        asm volatile("cp.async.commit_group;");
    }

    int stcur = 0, stnext = 2;
    for (int kt = 0; kt < nk; kt++) {
        if (kt + 2 < nk)
            asm volatile("cp.async.wait_group 1;");
        else
            asm volatile("cp.async.wait_group 0;");
        __syncthreads();

        if (kt + 2 < nk) {
            const size_t kb = (size_t)(kt + 2) * HBK * 2;
            const uint32_t dA = sb + stnext * STAGE_BYTES;
            const uint32_t dB = dA + HBM * HROWB;
            #pragma unroll
            for (int i = 0; i < 8; i++) {
                int r = ldr + 16 * i;
                cpa16s(dA + r * HROWB + ldch, Ab + (size_t)r * K * 2 + kb + ldch);
                cpa16s(dB + r * HROWB + ldch, Bb + (size_t)r * K * 2 + kb + ldch);
            }
            asm volatile("cp.async.commit_group;");
        }

        const uint32_t buf = sb + stcur * STAGE_BYTES;

        #pragma unroll
        for (int ks = 0; ks < 4; ks++) {
            uint32_t a[4][4], b[4][4];
            #pragma unroll
            for (int mt = 0; mt < 4; mt++)
                LDSM_X4(a[mt][0], a[mt][1], a[mt][2], a[mt][3],
                        buf + aOff[mt] + ks * 32);
            #pragma unroll
            for (int ntp = 0; ntp < 4; ntp++)
                LDSM_X4(b[ntp][0], b[ntp][1], b[ntp][2], b[ntp][3],
                        buf + bOff[ntp] + ks * 32);
            #pragma unroll
            for (int mt = 0; mt < 4; mt++)
                #pragma unroll
                for (int nt = 0; nt < 8; nt++)
                    mma_f16(c[mt][nt], a[mt][0], a[mt][1], a[mt][2], a[mt][3],
                            b[nt >> 1][(nt & 1) * 2], b[nt >> 1][(nt & 1) * 2 + 1]);
        }

        stcur  = (stcur == 2)  ? 0 : stcur + 1;
        stnext = (stnext == 2) ? 0 : stnext + 1;
    }

    #pragma unroll
    for (int mt = 0; mt < 4; mt++) {
        #pragma unroll
        for (int nt = 0; nt < 8; nt++) {
            int row = m0 + wm + mt * 16 + lr;
            int col = n0 + wn + nt * 8 + 2 * lc;
            if (HALF_OUT) {
                __half* C = (__half*)Cv;
                *(uint32_t*)(C + (size_t)row * N + col)       = packh2(c[mt][nt][0], c[mt][nt][1]);
                *(uint32_t*)(C + (size_t)(row + 8) * N + col) = packh2(c[mt][nt][2], c[mt][nt][3]);
            } else {
                float* C = (float*)Cv;
                *(float2*)(C + (size_t)row * N + col)       = make_float2(c[mt][nt][0], c[mt][nt][1]);
                *(float2*)(C + (size_t)(row + 8) * N + col) = make_float2(c[mt][nt][2], c[mt][nt][3]);
            }
        }
    }
}

// ---------------------------------------------------------------------------
// Fused RoPE, IN PLACE on qkvh (Q and K regions; V untouched).
// Q pre-scaled by (1/sqrt(d)) * log2(e) for base-2 softmax.
// ---------------------------------------------------------------------------
__global__ void rope_f16(__half* __restrict__ QKV)
{
    int idx = blockIdx.x * blockDim.x + threadIdx.x;
    if (idx >= MROWS * N_HEADS * 32) return;
    int j2  = idx & 31;
    int j   = 2 * j2;
    int h   = (idx >> 5) & (N_HEADS - 1);
    int row = idx >> 9;
    int s   = row & (SEQ - 1);

    const float c0 = 13.287712379549449f / 64.0f;
    float sn0, cs0, sn1, cs1;
    sincosf((float)s * exp2f(-(float)j * c0),       &sn0, &cs0);
    sincosf((float)s * exp2f(-(float)(j + 1) * c0), &sn1, &cs1);
    // 1/sqrt(128) * log2(e)
    const float scale = 0.088388347648318447f * 1.4426950408889634f;

    size_t bin = (size_t)row * NQKV + h * HEAD_DIM + j;

    __half2 qlo = *(const __half2*)(QKV + bin);
    __half2 qhi = *(const __half2*)(QKV + bin + 64);
    float2 q1 = __half22float2(qlo), q2 = __half22float2(qhi);
    *(uint32_t*)(QKV + bin)      = packh2((q1.x * cs0 - q2.x * sn0) * scale,
                                          (q1.y * cs1 - q2.y * sn1) * scale);
    *(uint32_t*)(QKV + bin + 64) = packh2((q2.x * cs0 + q1.x * sn0) * scale,
                                          (q2.y * cs1 + q1.y * sn1) * scale);

    __half2 klo = *(const __half2*)(QKV + bin + D_MODEL);
    __half2 khi = *(const __half2*)(QKV + bin + D_MODEL + 64);
    float2 k1 = __half22float2(klo), k2 = __half22float2(khi);
    *(uint32_t*)(QKV + bin + D_MODEL)      = packh2(k1.x * cs0 - k2.x * sn0,
                                                    k1.y * cs1 - k2.y * sn1);
    *(uint32_t*)(QKV + bin + D_MODEL + 64) = packh2(k2.x * cs0 + k1.x * sn0,
                                                    k2.y * cs1 + k1.y * sn1);
}

// ---------------------------------------------------------------------------
// Flash attention, fp16 mma, base-2 softmax, fused exp/PV interleave.
// 64 q-rows/block, 4 warps, 2 CTA/SM. Mask applied only on diagonal tile.
// ---------------------------------------------------------------------------
#define QSH 136
#define AQ_ROWS 64
#define OFF_KV (AQ_ROWS*QSH)               // halves
#define KVBUF  (64*QSH)
#define ATTN_SMEM_BYTES ((AQ_ROWS*QSH + 4*KVBUF) * 2)   // 87040

__global__ __launch_bounds__(128, 2) void attn_f16(const __half* __restrict__ QKV,
                                                   __half* __restrict__ O)
{
    extern __shared__ char smraw[];
    const uint32_t sb = s2u(smraw);

    const int tid  = threadIdx.x;
    const int warp = tid >> 5;
    const int lane = tid & 31;
    const int lr = lane >> 2;
    const int lc = lane & 3;
    const int wm = warp * 16;

    const int qx = gridDim.x - 1 - blockIdx.x;   // heavy CTAs first
    const int q0 = qx * AQ_ROWS;
    const int b  = blockIdx.y >> 4;
    const int h  = blockIdx.y & (N_HEADS - 1);

    const __half* Qb = QKV + ((size_t)(b * SEQ + q0)) * NQKV + h * HEAD_DIM;
    const __half* Kb = QKV + ((size_t)(b * SEQ)) * NQKV + D_MODEL + h * HEAD_DIM;
    const __half* Vb = QKV + ((size_t)(b * SEQ)) * NQKV + 2 * D_MODEL + h * HEAD_DIM;

    const uint32_t aQoff = ((wm + (lane & 15)) * QSH + ((lane & 16) ? 8 : 0)) * 2;
    uint32_t bKoff[4];
    #pragma unroll
    for (int ntp = 0; ntp < 4; ntp++)
        bKoff[ntp] = (((2 * ntp + ((lane & 16) ? 1 : 0)) * 8 + (lane & 7)) * QSH
                      + ((lane & 8) ? 8 : 0)) * 2;
    uint32_t bVoff[8];
    #pragma unroll
    for (int ntp = 0; ntp < 8; ntp++)
        bVoff[ntp] = ((lane & 15) * QSH + (2 * ntp + ((lane & 16) ? 1 : 0)) * 8) * 2;

    {
        #pragma unroll
        for (int i = 0; i < 8; i++) {
            int p = tid + 128 * i;
            int r = p >> 4, ch = p & 15;
            cpa16s(sb + (r * QSH) * 2 + ch * 16, Qb + (size_t)r * NQKV + ch * 8);
            cpa16s(sb + (OFF_KV + r * QSH) * 2 + ch * 16,         Kb + (size_t)r * NQKV + ch * 8);
            cpa16s(sb + (OFF_KV + KVBUF + r * QSH) * 2 + ch * 16, Vb + (size_t)r * NQKV + ch * 8);
        }
        asm volatile("cp.async.commit_group;");
    }

    uint32_t qf[8][4];
    float o_acc[16][4];
    #pragma unroll
    for (int i = 0; i < 16; i++)
        #pragma unroll
        for (int e = 0; e < 4; e++) o_acc[i][e] = 0.f;
    float m0 = -1e30f, m1 = -1e30f, l0 = 0.f, l1 = 0.f;

    const int r0g = q0 + wm + lr;
    const int r1g = r0g + 8;

    const int ntiles = qx + 1;
    for (int kt = 0; kt < ntiles; kt++) {
        asm volatile("cp.async.wait_group 0;");
        __syncthreads();

        if (kt == 0) {
            #pragma unroll
            for (int ks = 0; ks < 8; ks++)
                LDSM_X4(qf[ks][0], qf[ks][1], qf[ks][2], qf[ks][3],
                        sb + aQoff + ks * 32);
        }

        if (kt + 1 < ntiles) {
            const int nb = (kt + 1) & 1;
            const uint32_t dK = sb + (OFF_KV + nb * 2 * KVBUF) * 2;
            const uint32_t dV = dK + KVBUF * 2;
            const size_t krow = (size_t)(kt + 1) * 64;
            #pragma unroll
            for (int i = 0; i < 8; i++) {
                int p = tid + 128 * i;
                int r = p >> 4, ch = p & 15;
                cpa16s(dK + (r * QSH) * 2 + ch * 16, Kb + (krow + r) * NQKV + ch * 8);
                cpa16s(dV + (r * QSH) * 2 + ch * 16, Vb + (krow + r) * NQKV + ch * 8);
            }
            asm volatile("cp.async.commit_group;");
        }

        const uint32_t bufK = sb + (OFF_KV + (kt & 1) * 2 * KVBUF) * 2;
        const uint32_t bufV = bufK + KVBUF * 2;
        const int k0 = kt * 64;

        float s[8][4];
        #pragma unroll
        for (int nt = 0; nt < 8; nt++)
            #pragma unroll
            for (int e = 0; e < 4; e++) s[nt][e] = 0.f;

        #pragma unroll
        for (int ks = 0; ks < 8; ks++) {
            #pragma unroll
            for (int ntp = 0; ntp < 4; ntp++) {
                uint32_t b0, b1, b2, b3;
                LDSM_X4(b0, b1, b2, b3, bufK + bKoff[ntp] + ks * 32);
                mma_f16(s[2 * ntp],     qf[ks][0], qf[ks][1], qf[ks][2], qf[ks][3], b0, b1);
                mma_f16(s[2 * ntp + 1], qf[ks][0], qf[ks][1], qf[ks][2], qf[ks][3], b2, b3);
            }
        }

        // causal mask: only the diagonal tile needs it
        if (kt == ntiles - 1) {
            #pragma unroll
            for (int nt = 0; nt < 8; nt++) {
                int c0 = k0 + nt * 8 + 2 * lc;
                if (c0     > r0g) s[nt][0] = -1e30f;
                if (c0 + 1 > r0g) s[nt][1] = -1e30f;
                if (c0     > r1g) s[nt][2] = -1e30f;
                if (c0 + 1 > r1g) s[nt][3] = -1e30f;
            }
        }

        float rm0 = -1e30f, rm1 = -1e30f;
        #pragma unroll
        for (int nt = 0; nt < 8; nt++) {
            rm0 = fmaxf(rm0, fmaxf(s[nt][0], s[nt][1]));
            rm1 = fmaxf(rm1, fmaxf(s[nt][2], s[nt][3]));
        }
        rm0 = fmaxf(rm0, __shfl_xor_sync(0xffffffffu, rm0, 1));
        rm0 = fmaxf(rm0, __shfl_xor_sync(0xffffffffu, rm0, 2));
        rm1 = fmaxf(rm1, __shfl_xor_sync(0xffffffffu, rm1, 1));
        rm1 = fmaxf(rm1, __shfl_xor_sync(0xffffffffu, rm1, 2));

        float mn0 = fmaxf(m0, rm0), mn1 = fmaxf(m1, rm1);
        float al0 = exp2f(m0 - mn0), al1 = exp2f(m1 - mn1);
        m0 = mn0; m1 = mn1;

        // rescale O first (overlaps with first V ldmatrix below)
        #pragma unroll
        for (int nt2 = 0; nt2 < 16; nt2++) {
            o_acc[nt2][0] *= al0; o_acc[nt2][1] *= al0;
            o_acc[nt2][2] *= al1; o_acc[nt2][3] *= al1;
        }

        // fused exp + PV: k-step j consumes P columns from s[2j], s[2j+1]
        float ps0 = 0.f, ps1 = 0.f;
        #pragma unroll
        for (int j = 0; j < 4; j++) {
            float p00a = exp2f(s[2*j][0] - mn0);
            float p01a = exp2f(s[2*j][1] - mn0);
            float p10a = exp2f(s[2*j][2] - mn1);
            float p11a = exp2f(s[2*j][3] - mn1);
            float p00b = exp2f(s[2*j+1][0] - mn0);
            float p01b = exp2f(s[2*j+1][1] - mn0);
            float p10b = exp2f(s[2*j+1][2] - mn1);
            float p11b = exp2f(s[2*j+1][3] - mn1);
            ps0 += p00a + p01a + p00b + p01b;
            ps1 += p10a + p11a + p10b + p11b;
            uint32_t a0 = packh2(p00a, p01a);
            uint32_t a1 = packh2(p10a, p11a);
            uint32_t a2 = packh2(p00b, p01b);
            uint32_t a3 = packh2(p10b, p11b);
            #pragma unroll
            for (int ntp = 0; ntp < 8; ntp++) {
                uint32_t b0, b1, b2, b3;
                LDSM_X4T(b0, b1, b2, b3, bufV + bVoff[ntp] + j * 16 * QSH * 2);
                mma_f16(o_acc[2 * ntp],     a0, a1, a2, a3, b0, b1);
                mma_f16(o_acc[2 * ntp + 1], a0, a1, a2, a3, b2, b3);
            }
        }
        ps0 += __shfl_xor_sync(0xffffffffu, ps0, 1);
        ps0 += __shfl_xor_sync(0xffffffffu, ps0, 2);
        ps1 += __shfl_xor_sync(0xffffffffu, ps1, 1);
        ps1 += __shfl_xor_sync(0xffffffffu, ps1, 2);
        l0 = l0 * al0 + ps0;
        l1 = l1 * al1 + ps1;
    }

    float inv0 = 1.0f / l0, inv1 = 1.0f / l1;
    __half* Ob = O + ((size_t)(b * SEQ + q0 + wm + lr)) * D_MODEL + h * HEAD_DIM;
    #pragma unroll
    for (int nt2 = 0; nt2 < 16; nt2++) {
        int col = nt2 * 8 + 2 * lc;
        *(uint32_t*)(Ob + col)               = packh2(o_acc[nt2][0] * inv0, o_acc[nt2][1] * inv0);
        *(uint32_t*)(Ob + 8 * D_MODEL + col) = packh2(o_acc[nt2][2] * inv1, o_acc[nt2][3] * inv1);
    }
}

// ---------------------------------------------------------------------------
extern "C" void kernel_launch(void* const* d_in, const int* in_sizes, int n_in,
                              void* d_out, int out_size)
{
    const float* X  = (const float*)d_in[0];
    const float* Wq = (const float*)d_in[1];
    const float* Wk = (const float*)d_in[2];
    const float* Wv = (const float*)d_in[3];
    const float* Wo = (const float*)d_in[4];
    float* out = (float*)d_out;

    __half *qkvh, *xh, *oh, *wh;
    cudaGetSymbolAddress((void**)&qkvh, g_qkvh);
    cudaGetSymbolAddress((void**)&xh, g_xh);
    cudaGetSymbolAddress((void**)&oh, g_oh);
    cudaGetSymbolAddress((void**)&wh, g_wh);
    __half* woh = wh + 3 * (size_t)D_MODEL * D_MODEL;

    cudaFuncSetAttribute(attn_f16, cudaFuncAttributeMaxDynamicSharedMemorySize,
                         ATTN_SMEM_BYTES);
    cudaFuncSetAttribute(gemm_f16<true>, cudaFuncAttributeMaxDynamicSharedMemorySize,
                         GEMMH_SMEM);
    cudaFuncSetAttribute(gemm_f16<false>, cudaFuncAttributeMaxDynamicSharedMemorySize,
                         GEMMH_SMEM);

    // 1) fp16 conversion of all operands, single launch
    {
        int ntot = NX4 + 4 * NW4;
        f2h_all<<<(ntot + 255) / 256, 256>>>(
            (const float4*)X, (const float4*)Wq, (const float4*)Wk,
            (const float4*)Wv, (const float4*)Wo, (uint2*)xh, (uint2*)wh);
    }

    // 2) fused QKV projection
    gemm_f16<true><<<dim3(NQKV / 128, MROWS / HBM), 128, GEMMH_SMEM>>>(
        xh, wh, qkvh, MROWS, NQKV, D_MODEL);

    // 3) fused RoPE in place on qkvh (Q pre-scale incl. log2e)
    rope_f16<<<(MROWS * N_HEADS * 32) / 256, 256>>>(qkvh);

    // 4) attention (fused exp/PV interleave; base-2 softmax; 2 CTAs/SM)
    attn_f16<<<dim3(SEQ / AQ_ROWS, BATCH * N_HEADS), 128, ATTN_SMEM_BYTES>>>(qkvh, oh);

    // 5) output projection (fp32 out)
    gemm_f16<false><<<dim3(D_MODEL / 128, MROWS / HBM), 128, GEMMH_SMEM>>>(
        oh, woh, out, MROWS, D_MODEL, D_MODEL);
}